// round 8
// baseline (speedup 1.0000x reference)
#include <cuda_runtime.h>
#include <cuda_bf16.h>
typedef __nv_bfloat16 bf;

#define B_   16
#define D_   448
#define HW_  4096
#define DSQ  (D_*D_)
#define BIG  (16L*D_*HW_)
#define NOUT (16L*448L*4096L)
#define NPART 7168
#define MSMEM 65536

// ---------------- device scratch ----------------
__device__ alignas(16) bf g_VsH[BIG], g_VsL[BIG], g_VrH[BIG], g_VrL[BIG];
__device__ float g_G[32L*DSQ];   // gram: [0..15]=pos (SIMT), [16..31]=neg (MMA)
__device__ float g_T[32L*DSQ];
__device__ float g_S[32L*DSQ];
__device__ float g_A[32L*DSQ];
__device__ float g_part[NPART];

// ---- packed fp32x2 helpers (known-good R1) ----
__device__ __forceinline__ unsigned long long pk2(float v){
  unsigned long long r; asm("mov.b64 %0, {%1, %1};" : "=l"(r) : "f"(v)); return r;
}
__device__ __forceinline__ void fma2(unsigned long long &d, unsigned long long a, unsigned long long b){
  asm("fma.rn.f32x2 %0, %1, %2, %0;" : "+l"(d) : "l"(a), "l"(b));
}
__device__ __forceinline__ float2 up2(unsigned long long v){
  float2 f; asm("mov.b64 {%0, %1}, %2;" : "=f"(f.x), "=f"(f.y) : "l"(v)); return f;
}

// ---- mma helpers (sm_80-baseline; NO cp.async this time) ----
__device__ __forceinline__ unsigned su32(const void* p){ return (unsigned)__cvta_generic_to_shared(p); }
__device__ __forceinline__ void ldsm4(unsigned* r, unsigned a){
  asm volatile("ldmatrix.sync.aligned.m8n8.x4.shared.b16 {%0,%1,%2,%3}, [%4];"
    : "=r"(r[0]),"=r"(r[1]),"=r"(r[2]),"=r"(r[3]) : "r"(a));
}
__device__ __forceinline__ void mma16816(float* c, const unsigned* a, unsigned b0, unsigned b1){
  asm volatile("mma.sync.aligned.m16n8k16.row.col.f32.bf16.bf16.f32 "
    "{%0,%1,%2,%3}, {%4,%5,%6,%7}, {%8,%9}, {%0,%1,%2,%3};"
    : "+f"(c[0]),"+f"(c[1]),"+f"(c[2]),"+f"(c[3])
    : "r"(a[0]),"r"(a[1]),"r"(a[2]),"r"(a[3]), "r"(b0),"r"(b1));
}
__device__ __forceinline__ unsigned sw(unsigned off){ return off ^ ((off >> 3) & 0x70u); }

// ---- bf16 hi/lo split ----
__global__ void __launch_bounds__(256) split_pair(const float* __restrict__ s,
                                                  bf* __restrict__ h, bf* __restrict__ l, long n4)
{
  for (long i = blockIdx.x * 256L + threadIdx.x; i < n4; i += (long)gridDim.x * 256L){
    float4 x = ((const float4*)s)[i];
    bf h0=__float2bfloat16(x.x), h1=__float2bfloat16(x.y), h2=__float2bfloat16(x.z), h3=__float2bfloat16(x.w);
    __nv_bfloat162 a, bq; a.x=h0; a.y=h1; bq.x=h2; bq.y=h3;
    ((__nv_bfloat162*)h)[2*i] = a; ((__nv_bfloat162*)h)[2*i+1] = bq;
    __nv_bfloat162 cc, dd;
    cc.x=__float2bfloat16(x.x-__bfloat162float(h0)); cc.y=__float2bfloat16(x.y-__bfloat162float(h1));
    dd.x=__float2bfloat16(x.z-__bfloat162float(h2)); dd.y=__float2bfloat16(x.w-__bfloat162float(h3));
    ((__nv_bfloat162*)l)[2*i] = cc; ((__nv_bfloat162*)l)[2*i+1] = dd;
  }
}

// ---- MMA neg-gram: G[16+z] = (VsH+VsL)[b] @ (VrH+VrL)[(b+1)%16]^T ----
// Synchronous single-stage smem (LDG+STS), ldmatrix + mma.sync, 128x128 tiles.
__global__ void __launch_bounds__(256) gram_mma_neg()
{
  extern __shared__ char raw[];
  unsigned rbase = su32(raw);
  char* dsm = raw + (((rbase + 1023u) & ~1023u) - rbase);
  const int tid = threadIdx.x, lane = tid & 31, wid = tid >> 5;
  const int wm = wid >> 2, wn = wid & 3;
  const int b = blockIdx.z, b2 = (b + 1) & 15;
  const int m0 = blockIdx.x * 128, n0 = blockIdx.y * 128;
  const bf* Ah = g_VsH + (long)b  * D_ * HW_;
  const bf* Al = g_VsL + (long)b  * D_ * HW_;
  const bf* Bh = g_VrH + (long)b2 * D_ * HW_;
  const bf* Bl = g_VrL + (long)b2 * D_ * HW_;

  float acc[4][4][4];
#pragma unroll
  for (int mi = 0; mi < 4; ++mi)
#pragma unroll
    for (int ni = 0; ni < 4; ++ni)
#pragma unroll
      for (int q = 0; q < 4; ++q) acc[mi][ni][q] = 0.f;

  unsigned sb = su32(dsm);
  for (int c = 0; c < 64; ++c){
    int k0 = c << 6;
    __syncthreads();   // protect previous iteration's reads
#pragma unroll
    for (int j = 0; j < 4; ++j){
      int i = tid + j * 256;
      int r = i >> 3, v = i & 7;
      unsigned off = sw((unsigned)(r * 128 + v * 16));
      int ra = m0 + r; if (ra > D_ - 1) ra = D_ - 1;
      long ea = (long)ra * HW_ + k0 + v * 8;
      *(uint4*)(dsm + off)         = *(const uint4*)(Ah + ea);
      *(uint4*)(dsm + 16384 + off) = *(const uint4*)(Al + ea);
      int rb = n0 + r; if (rb > D_ - 1) rb = D_ - 1;
      long eb = (long)rb * HW_ + k0 + v * 8;
      *(uint4*)(dsm + 32768 + off) = *(const uint4*)(Bh + eb);
      *(uint4*)(dsm + 49152 + off) = *(const uint4*)(Bl + eb);
    }
    __syncthreads();
#pragma unroll
    for (int k16 = 0; k16 < 4; ++k16){
      unsigned ah[4][4], al[4][4], bh[2][4], bl[2][4];
      unsigned cb = (unsigned)(k16 * 32 + ((lane >> 4) << 4));
#pragma unroll
      for (int mi = 0; mi < 4; ++mi){
        unsigned off = sw((unsigned)((wm * 64 + mi * 16 + (lane & 15)) * 128 + cb));
        ldsm4(ah[mi], sb + off);
        ldsm4(al[mi], sb + 16384 + off);
      }
#pragma unroll
      for (int nb = 0; nb < 2; ++nb){
        unsigned off = sw((unsigned)((wn * 32 + nb * 16 + ((lane >> 3) & 1) * 8 + (lane & 7)) * 128 + cb));
        ldsm4(bh[nb], sb + 32768 + off);
        ldsm4(bl[nb], sb + 49152 + off);
      }
#pragma unroll
      for (int mi = 0; mi < 4; ++mi)
#pragma unroll
        for (int ni = 0; ni < 4; ++ni){
          int nb = ni >> 1, sel = ni & 1;
          float* cc = acc[mi][ni];
          mma16816(cc, ah[mi], bh[nb][sel], bh[nb][sel + 2]);
          mma16816(cc, ah[mi], bl[nb][sel], bl[nb][sel + 2]);
          mma16816(cc, al[mi], bh[nb][sel], bh[nb][sel + 2]);
        }
    }
  }

  float* Cg = g_G + (long)(16 + b) * DSQ;
#pragma unroll
  for (int mi = 0; mi < 4; ++mi)
#pragma unroll
    for (int ni = 0; ni < 4; ++ni){
      float* c = acc[mi][ni];
      int r = m0 + wm * 64 + mi * 16 + (lane >> 2);
      int n = n0 + wn * 32 + ni * 8 + ((lane & 3) << 1);
      if (n < D_){
        if (r < D_)     *(float2*)(Cg + (long)r * D_ + n)       = make_float2(c[0], c[1]);
        if (r + 8 < D_) *(float2*)(Cg + (long)(r + 8) * D_ + n) = make_float2(c[2], c[3]);
      }
    }
}

// ================= R1 known-good SIMT pipeline (verbatim) =================
template<bool NT>
__device__ __forceinline__ void gemm_body(const float* __restrict__ A, const float* __restrict__ B,
                                          float* __restrict__ C, int K, int lda, int ldb, int ldc,
                                          float scale)
{
  __shared__ float As[16][68];
  __shared__ float Bs[16][68];
  const int tid = threadIdx.x;
  const int tx = tid & 15, ty = tid >> 4;
  const int m0 = blockIdx.x * 64, n0 = blockIdx.y * 64;
  unsigned long long acc[4][2];
#pragma unroll
  for (int i = 0; i < 4; i++) { acc[i][0] = 0ull; acc[i][1] = 0ull; }
  const int ra = tid >> 2, ka = tid & 3;
  const int kb = tid >> 4, nb = tid & 15;

  for (int k0 = 0; k0 < K; k0 += 16) {
    float4 av = *(const float4*)(A + (long)(m0 + ra) * lda + k0 + ka * 4);
    As[ka*4+0][ra] = av.x; As[ka*4+1][ra] = av.y; As[ka*4+2][ra] = av.z; As[ka*4+3][ra] = av.w;
    if (NT) {
      float4 bv = *(const float4*)(B + (long)(n0 + ra) * ldb + k0 + ka * 4);
      Bs[ka*4+0][ra] = bv.x; Bs[ka*4+1][ra] = bv.y; Bs[ka*4+2][ra] = bv.z; Bs[ka*4+3][ra] = bv.w;
    } else {
      *(float4*)&Bs[kb][nb*4] = *(const float4*)(B + (long)(k0 + kb) * ldb + n0 + nb * 4);
    }
    __syncthreads();
#pragma unroll
    for (int k = 0; k < 16; k++) {
      float4 a = *(const float4*)&As[k][ty*4];
      ulonglong2 bb = *(const ulonglong2*)&Bs[k][tx*4];
      unsigned long long a0 = pk2(a.x), a1 = pk2(a.y), a2 = pk2(a.z), a3 = pk2(a.w);
      fma2(acc[0][0], a0, bb.x); fma2(acc[0][1], a0, bb.y);
      fma2(acc[1][0], a1, bb.x); fma2(acc[1][1], a1, bb.y);
      fma2(acc[2][0], a2, bb.x); fma2(acc[2][1], a2, bb.y);
      fma2(acc[3][0], a3, bb.x); fma2(acc[3][1], a3, bb.y);
    }
    __syncthreads();
  }
#pragma unroll
  for (int i = 0; i < 4; i++) {
    float2 lo = up2(acc[i][0]), hi = up2(acc[i][1]);
    float4 o = make_float4(lo.x*scale, lo.y*scale, hi.x*scale, hi.y*scale);
    *(float4*)(C + (long)(m0 + ty*4 + i) * ldc + n0 + tx*4) = o;
  }
}

// pos gram only (z = 0..15), SIMT — guarantees output-0 correctness path
__global__ void __launch_bounds__(256) gram_pos(const float* __restrict__ Vs,
                                                const float* __restrict__ Vr)
{
  int b = blockIdx.z;
  gemm_body<true>(Vs + (long)b * D_ * HW_, Vr + (long)b * D_ * HW_,
                  g_G + (long)b * DSQ, HW_, HW_, HW_, D_, 1.0f);
}

__global__ void __launch_bounds__(256) gkt_kernel(const float* __restrict__ Wk)
{
  int z = blockIdx.z;
  gemm_body<true>(g_G + (long)z * DSQ, Wk, g_T + (long)z * DSQ, D_, D_, D_, D_, 1.0f);
}

__global__ void __launch_bounds__(256) wqt_kernel(const float* __restrict__ Wq)
{
  int z = blockIdx.z;
  const float SCALE = 0.047245559f;
  gemm_body<false>(Wq, g_T + (long)z * DSQ, g_S + (long)z * DSQ, D_, D_, D_, D_, SCALE);
}

__global__ void __launch_bounds__(256) softmax_kernel()
{
  int warp = (blockIdx.x * blockDim.x + threadIdx.x) >> 5;
  int lane = threadIdx.x & 31;
  if (warp >= 32 * D_) return;
  float* row = g_S + (long)warp * D_;
  float v[14];
  float mx = -1e30f;
#pragma unroll
  for (int i = 0; i < 14; i++) { v[i] = row[lane + i * 32]; mx = fmaxf(mx, v[i]); }
#pragma unroll
  for (int o = 16; o; o >>= 1) mx = fmaxf(mx, __shfl_xor_sync(0xffffffffu, mx, o));
  float s = 0.f;
#pragma unroll
  for (int i = 0; i < 14; i++) { v[i] = __expf(v[i] - mx); s += v[i]; }
#pragma unroll
  for (int o = 16; o; o >>= 1) s += __shfl_xor_sync(0xffffffffu, s, o);
  float inv = 1.0f / s;
#pragma unroll
  for (int i = 0; i < 14; i++) row[lane + i * 32] = v[i] * inv;
}

__global__ void __launch_bounds__(256) av_kernel(const float* __restrict__ Wv)
{
  int z = blockIdx.z;
  gemm_body<false>(g_S + (long)z * DSQ, Wv, g_A + (long)z * DSQ, D_, D_, D_, D_, 1.0f);
}

__global__ void __launch_bounds__(256) final_kernel(const float* __restrict__ Vr,
                                                    const float* __restrict__ Vs,
                                                    float* __restrict__ out)
{
  __shared__ float Ap[16][68];
  __shared__ float An[16][68];
  __shared__ float Bs[16][68];
  const int b = blockIdx.z;
  const float* Apos = g_A + (long)b * DSQ;
  const float* Aneg = g_A + (long)(16 + b) * DSQ;
  const float* Bm   = Vr + (long)b * D_ * HW_;
  const int tid = threadIdx.x;
  const int tx = tid & 15, ty = tid >> 4;
  const int m0 = blockIdx.x * 64, n0 = blockIdx.y * 64;
  unsigned long long accP[4][2], accN[4][2];
#pragma unroll
  for (int i = 0; i < 4; i++) { accP[i][0]=0ull; accP[i][1]=0ull; accN[i][0]=0ull; accN[i][1]=0ull; }
  const int ra = tid >> 2, ka = tid & 3;
  const int kb = tid >> 4, nb = tid & 15;

  for (int k0 = 0; k0 < D_; k0 += 16) {
    float4 av = *(const float4*)(Apos + (long)(m0 + ra) * D_ + k0 + ka * 4);
    Ap[ka*4+0][ra] = av.x; Ap[ka*4+1][ra] = av.y; Ap[ka*4+2][ra] = av.z; Ap[ka*4+3][ra] = av.w;
    float4 nv = *(const float4*)(Aneg + (long)(m0 + ra) * D_ + k0 + ka * 4);
    An[ka*4+0][ra] = nv.x; An[ka*4+1][ra] = nv.y; An[ka*4+2][ra] = nv.z; An[ka*4+3][ra] = nv.w;
    *(float4*)&Bs[kb][nb*4] = *(const float4*)(Bm + (long)(k0 + kb) * HW_ + n0 + nb * 4);
    __syncthreads();
#pragma unroll
    for (int k = 0; k < 16; k++) {
      float4 ap = *(const float4*)&Ap[k][ty*4];
      float4 an = *(const float4*)&An[k][ty*4];
      ulonglong2 bb = *(const ulonglong2*)&Bs[k][tx*4];
      unsigned long long p0 = pk2(ap.x), p1 = pk2(ap.y), p2 = pk2(ap.z), p3 = pk2(ap.w);
      unsigned long long q0 = pk2(an.x), q1 = pk2(an.y), q2 = pk2(an.z), q3 = pk2(an.w);
      fma2(accP[0][0], p0, bb.x); fma2(accP[0][1], p0, bb.y);
      fma2(accP[1][0], p1, bb.x); fma2(accP[1][1], p1, bb.y);
      fma2(accP[2][0], p2, bb.x); fma2(accP[2][1], p2, bb.y);
      fma2(accP[3][0], p3, bb.x); fma2(accP[3][1], p3, bb.y);
      fma2(accN[0][0], q0, bb.x); fma2(accN[0][1], q0, bb.y);
      fma2(accN[1][0], q1, bb.x); fma2(accN[1][1], q1, bb.y);
      fma2(accN[2][0], q2, bb.x); fma2(accN[2][1], q2, bb.y);
      fma2(accN[3][0], q3, bb.x); fma2(accN[3][1], q3, bb.y);
    }
    __syncthreads();
  }

  float lsum = 0.f;
#pragma unroll
  for (int i = 0; i < 4; i++) {
    float2 pl = up2(accP[i][0]), ph = up2(accP[i][1]);
    float2 ql = up2(accN[i][0]), qh = up2(accN[i][1]);
    long idx = ((long)b * D_ + m0 + ty*4 + i) * HW_ + n0 + tx*4;
    float4 vs = *(const float4*)(Vs + idx);
    float4 o = make_float4(vs.x + pl.x, vs.y + pl.y, vs.z + ph.x, vs.w + ph.y);
    *(float4*)(out + idx) = o;
    lsum += fmaxf(ql.x - pl.x + 12.0f, 0.0f);
    lsum += fmaxf(ql.y - pl.y + 12.0f, 0.0f);
    lsum += fmaxf(qh.x - ph.x + 12.0f, 0.0f);
    lsum += fmaxf(qh.y - ph.y + 12.0f, 0.0f);
  }
  __shared__ float red[256];
  red[tid] = lsum;
  __syncthreads();
  for (int s = 128; s; s >>= 1) {
    if (tid < s) red[tid] += red[tid + s];
    __syncthreads();
  }
  if (tid == 0)
    g_part[blockIdx.z * (gridDim.x * gridDim.y) + blockIdx.x * gridDim.y + blockIdx.y] = red[0];
}

__global__ void __launch_bounds__(256) loss_reduce(float* __restrict__ out, int out_size)
{
  __shared__ float red[256];
  int tid = threadIdx.x;
  float s = 0.f;
  for (int i = tid; i < NPART; i += 256) s += g_part[i];
  red[tid] = s;
  __syncthreads();
  for (int st = 128; st; st >>= 1) {
    if (tid < st) red[tid] += red[tid + st];
    __syncthreads();
  }
  if (tid == 0 && (long)out_size > NOUT)
    out[NOUT] = red[0] / (float)(16.0 * 448.0 * 4096.0);
}

extern "C" void kernel_launch(void* const* d_in, const int* in_sizes, int n_in,
                              void* d_out, int out_size)
{
  (void)in_sizes; (void)n_in;
  const float* V_r = (const float*)d_in[0];
  const float* V_s = (const float*)d_in[1];
  const float* W_q = (const float*)d_in[2];
  const float* W_k = (const float*)d_in[3];
  const float* W_v = (const float*)d_in[4];
  float* out = (float*)d_out;

  cudaFuncSetAttribute(gram_mma_neg, cudaFuncAttributeMaxDynamicSharedMemorySize, MSMEM + 1024);

  dim3 blk(256);
  split_pair<<<512, blk>>>(V_s, g_VsH, g_VsL, BIG / 4);
  split_pair<<<512, blk>>>(V_r, g_VrH, g_VrL, BIG / 4);
  gram_pos    <<<dim3(7, 7, 16), blk>>>(V_s, V_r);              // pos gram: SIMT (output-0 path)
  gram_mma_neg<<<dim3(4, 4, 16), blk, MSMEM + 1024>>>();        // neg gram: MMA (loss-only path)
  gkt_kernel<<<dim3(7, 7, 32), blk>>>(W_k);
  wqt_kernel<<<dim3(7, 7, 32), blk>>>(W_q);
  softmax_kernel<<<1792,       blk>>>();
  av_kernel <<<dim3(7, 7, 32), blk>>>(W_v);
  final_kernel<<<dim3(7, 64, 16), blk>>>(V_r, V_s, out);
  loss_reduce <<<1,            blk>>>(out, out_size);
}

// round 9
// speedup vs baseline: 1.0198x; 1.0198x over previous
#include <cuda_runtime.h>
#include <cuda_bf16.h>
typedef __nv_bfloat16 bf;

#define B_   16
#define D_   448
#define HW_  4096
#define DSQ  (D_*D_)
#define BIG  (16L*D_*HW_)
#define NOUT (16L*448L*4096L)
#define NPART 7168
#define MSMEM 65536

// ---------------- device scratch ----------------
__device__ alignas(16) bf g_VsH[BIG], g_VsL[BIG], g_VrH[BIG], g_VrL[BIG];
__device__ float g_G[32L*DSQ];   // gram: [0..15]=pos (SIMT), [16..31]=neg (MMA)
__device__ float g_T[32L*DSQ];
__device__ float g_S[32L*DSQ];
__device__ float g_A[32L*DSQ];
__device__ float g_part[NPART];

// ---- packed fp32x2 helpers (known-good R1) ----
__device__ __forceinline__ unsigned long long pk2(float v){
  unsigned long long r; asm("mov.b64 %0, {%1, %1};" : "=l"(r) : "f"(v)); return r;
}
__device__ __forceinline__ void fma2(unsigned long long &d, unsigned long long a, unsigned long long b){
  asm("fma.rn.f32x2 %0, %1, %2, %0;" : "+l"(d) : "l"(a), "l"(b));
}
__device__ __forceinline__ float2 up2(unsigned long long v){
  float2 f; asm("mov.b64 {%0, %1}, %2;" : "=f"(f.x), "=f"(f.y) : "l"(v)); return f;
}

// ---- mma helpers (sm_80-baseline; NO cp.async this time) ----
__device__ __forceinline__ unsigned su32(const void* p){ return (unsigned)__cvta_generic_to_shared(p); }
__device__ __forceinline__ void ldsm4(unsigned* r, unsigned a){
  asm volatile("ldmatrix.sync.aligned.m8n8.x4.shared.b16 {%0,%1,%2,%3}, [%4];"
    : "=r"(r[0]),"=r"(r[1]),"=r"(r[2]),"=r"(r[3]) : "r"(a));
}
__device__ __forceinline__ void mma16816(float* c, const unsigned* a, unsigned b0, unsigned b1){
  asm volatile("mma.sync.aligned.m16n8k16.row.col.f32.bf16.bf16.f32 "
    "{%0,%1,%2,%3}, {%4,%5,%6,%7}, {%8,%9}, {%0,%1,%2,%3};"
    : "+f"(c[0]),"+f"(c[1]),"+f"(c[2]),"+f"(c[3])
    : "r"(a[0]),"r"(a[1]),"r"(a[2]),"r"(a[3]), "r"(b0),"r"(b1));
}
__device__ __forceinline__ unsigned sw(unsigned off){ return off ^ ((off >> 3) & 0x70u); }

// ---- bf16 hi/lo split ----
__global__ void __launch_bounds__(256) split_pair(const float* __restrict__ s,
                                                  bf* __restrict__ h, bf* __restrict__ l, long n4)
{
  for (long i = blockIdx.x * 256L + threadIdx.x; i < n4; i += (long)gridDim.x * 256L){
    float4 x = ((const float4*)s)[i];
    bf h0=__float2bfloat16(x.x), h1=__float2bfloat16(x.y), h2=__float2bfloat16(x.z), h3=__float2bfloat16(x.w);
    __nv_bfloat162 a, bq; a.x=h0; a.y=h1; bq.x=h2; bq.y=h3;
    ((__nv_bfloat162*)h)[2*i] = a; ((__nv_bfloat162*)h)[2*i+1] = bq;
    __nv_bfloat162 cc, dd;
    cc.x=__float2bfloat16(x.x-__bfloat162float(h0)); cc.y=__float2bfloat16(x.y-__bfloat162float(h1));
    dd.x=__float2bfloat16(x.z-__bfloat162float(h2)); dd.y=__float2bfloat16(x.w-__bfloat162float(h3));
    ((__nv_bfloat162*)l)[2*i] = cc; ((__nv_bfloat162*)l)[2*i+1] = dd;
  }
}

// ---- MMA neg-gram: G[16+z] = (VsH+VsL)[b] @ (VrH+VrL)[(b+1)%16]^T ----
// Synchronous single-stage smem (LDG+STS), ldmatrix + mma.sync, 128x128 tiles.
__global__ void __launch_bounds__(256) gram_mma_neg()
{
  extern __shared__ char raw[];
  unsigned rbase = su32(raw);
  char* dsm = raw + (((rbase + 1023u) & ~1023u) - rbase);
  const int tid = threadIdx.x, lane = tid & 31, wid = tid >> 5;
  const int wm = wid >> 2, wn = wid & 3;
  const int b = blockIdx.z, b2 = (b + 1) & 15;
  const int m0 = blockIdx.x * 128, n0 = blockIdx.y * 128;
  const bf* Ah = g_VsH + (long)b  * D_ * HW_;
  const bf* Al = g_VsL + (long)b  * D_ * HW_;
  const bf* Bh = g_VrH + (long)b2 * D_ * HW_;
  const bf* Bl = g_VrL + (long)b2 * D_ * HW_;

  float acc[4][4][4];
#pragma unroll
  for (int mi = 0; mi < 4; ++mi)
#pragma unroll
    for (int ni = 0; ni < 4; ++ni)
#pragma unroll
      for (int q = 0; q < 4; ++q) acc[mi][ni][q] = 0.f;

  unsigned sb = su32(dsm);
  for (int c = 0; c < 64; ++c){
    int k0 = c << 6;
    __syncthreads();   // protect previous iteration's reads
#pragma unroll
    for (int j = 0; j < 4; ++j){
      int i = tid + j * 256;
      int r = i >> 3, v = i & 7;
      unsigned off = sw((unsigned)(r * 128 + v * 16));
      int ra = m0 + r; if (ra > D_ - 1) ra = D_ - 1;
      long ea = (long)ra * HW_ + k0 + v * 8;
      *(uint4*)(dsm + off)         = *(const uint4*)(Ah + ea);
      *(uint4*)(dsm + 16384 + off) = *(const uint4*)(Al + ea);
      int rb = n0 + r; if (rb > D_ - 1) rb = D_ - 1;
      long eb = (long)rb * HW_ + k0 + v * 8;
      *(uint4*)(dsm + 32768 + off) = *(const uint4*)(Bh + eb);
      *(uint4*)(dsm + 49152 + off) = *(const uint4*)(Bl + eb);
    }
    __syncthreads();
#pragma unroll
    for (int k16 = 0; k16 < 4; ++k16){
      unsigned ah[4][4], al[4][4], bh[2][4], bl[2][4];
      unsigned cb = (unsigned)(k16 * 32 + ((lane >> 4) << 4));
#pragma unroll
      for (int mi = 0; mi < 4; ++mi){
        unsigned off = sw((unsigned)((wm * 64 + mi * 16 + (lane & 15)) * 128 + cb));
        ldsm4(ah[mi], sb + off);
        ldsm4(al[mi], sb + 16384 + off);
      }
#pragma unroll
      for (int nb = 0; nb < 2; ++nb){
        unsigned off = sw((unsigned)((wn * 32 + nb * 16 + ((lane >> 3) & 1) * 8 + (lane & 7)) * 128 + cb));
        ldsm4(bh[nb], sb + 32768 + off);
        ldsm4(bl[nb], sb + 49152 + off);
      }
#pragma unroll
      for (int mi = 0; mi < 4; ++mi)
#pragma unroll
        for (int ni = 0; ni < 4; ++ni){
          int nb = ni >> 1, sel = ni & 1;
          float* cc = acc[mi][ni];
          mma16816(cc, ah[mi], bh[nb][sel], bh[nb][sel + 2]);
          mma16816(cc, ah[mi], bl[nb][sel], bl[nb][sel + 2]);
          mma16816(cc, al[mi], bh[nb][sel], bh[nb][sel + 2]);
        }
    }
  }

  float* Cg = g_G + (long)(16 + b) * DSQ;
#pragma unroll
  for (int mi = 0; mi < 4; ++mi)
#pragma unroll
    for (int ni = 0; ni < 4; ++ni){
      float* c = acc[mi][ni];
      int r = m0 + wm * 64 + mi * 16 + (lane >> 2);
      int n = n0 + wn * 32 + ni * 8 + ((lane & 3) << 1);
      if (n < D_){
        if (r < D_)     *(float2*)(Cg + (long)r * D_ + n)       = make_float2(c[0], c[1]);
        if (r + 8 < D_) *(float2*)(Cg + (long)(r + 8) * D_ + n) = make_float2(c[2], c[3]);
      }
    }
}

// ================= R1 known-good SIMT pipeline (verbatim) =================
template<bool NT>
__device__ __forceinline__ void gemm_body(const float* __restrict__ A, const float* __restrict__ B,
                                          float* __restrict__ C, int K, int lda, int ldb, int ldc,
                                          float scale)
{
  __shared__ float As[16][68];
  __shared__ float Bs[16][68];
  const int tid = threadIdx.x;
  const int tx = tid & 15, ty = tid >> 4;
  const int m0 = blockIdx.x * 64, n0 = blockIdx.y * 64;
  unsigned long long acc[4][2];
#pragma unroll
  for (int i = 0; i < 4; i++) { acc[i][0] = 0ull; acc[i][1] = 0ull; }
  const int ra = tid >> 2, ka = tid & 3;
  const int kb = tid >> 4, nb = tid & 15;

  for (int k0 = 0; k0 < K; k0 += 16) {
    float4 av = *(const float4*)(A + (long)(m0 + ra) * lda + k0 + ka * 4);
    As[ka*4+0][ra] = av.x; As[ka*4+1][ra] = av.y; As[ka*4+2][ra] = av.z; As[ka*4+3][ra] = av.w;
    if (NT) {
      float4 bv = *(const float4*)(B + (long)(n0 + ra) * ldb + k0 + ka * 4);
      Bs[ka*4+0][ra] = bv.x; Bs[ka*4+1][ra] = bv.y; Bs[ka*4+2][ra] = bv.z; Bs[ka*4+3][ra] = bv.w;
    } else {
      *(float4*)&Bs[kb][nb*4] = *(const float4*)(B + (long)(k0 + kb) * ldb + n0 + nb * 4);
    }
    __syncthreads();
#pragma unroll
    for (int k = 0; k < 16; k++) {
      float4 a = *(const float4*)&As[k][ty*4];
      ulonglong2 bb = *(const ulonglong2*)&Bs[k][tx*4];
      unsigned long long a0 = pk2(a.x), a1 = pk2(a.y), a2 = pk2(a.z), a3 = pk2(a.w);
      fma2(acc[0][0], a0, bb.x); fma2(acc[0][1], a0, bb.y);
      fma2(acc[1][0], a1, bb.x); fma2(acc[1][1], a1, bb.y);
      fma2(acc[2][0], a2, bb.x); fma2(acc[2][1], a2, bb.y);
      fma2(acc[3][0], a3, bb.x); fma2(acc[3][1], a3, bb.y);
    }
    __syncthreads();
  }
#pragma unroll
  for (int i = 0; i < 4; i++) {
    float2 lo = up2(acc[i][0]), hi = up2(acc[i][1]);
    float4 o = make_float4(lo.x*scale, lo.y*scale, hi.x*scale, hi.y*scale);
    *(float4*)(C + (long)(m0 + ty*4 + i) * ldc + n0 + tx*4) = o;
  }
}

// pos gram only (z = 0..15), SIMT — guarantees output-0 correctness path
__global__ void __launch_bounds__(256) gram_pos(const float* __restrict__ Vs,
                                                const float* __restrict__ Vr)
{
  int b = blockIdx.z;
  gemm_body<true>(Vs + (long)b * D_ * HW_, Vr + (long)b * D_ * HW_,
                  g_G + (long)b * DSQ, HW_, HW_, HW_, D_, 1.0f);
}

__global__ void __launch_bounds__(256) gkt_kernel(const float* __restrict__ Wk)
{
  int z = blockIdx.z;
  gemm_body<true>(g_G + (long)z * DSQ, Wk, g_T + (long)z * DSQ, D_, D_, D_, D_, 1.0f);
}

__global__ void __launch_bounds__(256) wqt_kernel(const float* __restrict__ Wq)
{
  int z = blockIdx.z;
  const float SCALE = 0.047245559f;
  gemm_body<false>(Wq, g_T + (long)z * DSQ, g_S + (long)z * DSQ, D_, D_, D_, D_, SCALE);
}

__global__ void __launch_bounds__(256) softmax_kernel()
{
  int warp = (blockIdx.x * blockDim.x + threadIdx.x) >> 5;
  int lane = threadIdx.x & 31;
  if (warp >= 32 * D_) return;
  float* row = g_S + (long)warp * D_;
  float v[14];
  float mx = -1e30f;
#pragma unroll
  for (int i = 0; i < 14; i++) { v[i] = row[lane + i * 32]; mx = fmaxf(mx, v[i]); }
#pragma unroll
  for (int o = 16; o; o >>= 1) mx = fmaxf(mx, __shfl_xor_sync(0xffffffffu, mx, o));
  float s = 0.f;
#pragma unroll
  for (int i = 0; i < 14; i++) { v[i] = __expf(v[i] - mx); s += v[i]; }
#pragma unroll
  for (int o = 16; o; o >>= 1) s += __shfl_xor_sync(0xffffffffu, s, o);
  float inv = 1.0f / s;
#pragma unroll
  for (int i = 0; i < 14; i++) row[lane + i * 32] = v[i] * inv;
}

__global__ void __launch_bounds__(256) av_kernel(const float* __restrict__ Wv)
{
  int z = blockIdx.z;
  gemm_body<false>(g_S + (long)z * DSQ, Wv, g_A + (long)z * DSQ, D_, D_, D_, D_, 1.0f);
}

__global__ void __launch_bounds__(256) final_kernel(const float* __restrict__ Vr,
                                                    const float* __restrict__ Vs,
                                                    float* __restrict__ out)
{
  __shared__ float Ap[16][68];
  __shared__ float An[16][68];
  __shared__ float Bs[16][68];
  const int b = blockIdx.z;
  const float* Apos = g_A + (long)b * DSQ;
  const float* Aneg = g_A + (long)(16 + b) * DSQ;
  const float* Bm   = Vr + (long)b * D_ * HW_;
  const int tid = threadIdx.x;
  const int tx = tid & 15, ty = tid >> 4;
  const int m0 = blockIdx.x * 64, n0 = blockIdx.y * 64;
  unsigned long long accP[4][2], accN[4][2];
#pragma unroll
  for (int i = 0; i < 4; i++) { accP[i][0]=0ull; accP[i][1]=0ull; accN[i][0]=0ull; accN[i][1]=0ull; }
  const int ra = tid >> 2, ka = tid & 3;
  const int kb = tid >> 4, nb = tid & 15;

  for (int k0 = 0; k0 < D_; k0 += 16) {
    float4 av = *(const float4*)(Apos + (long)(m0 + ra) * D_ + k0 + ka * 4);
    Ap[ka*4+0][ra] = av.x; Ap[ka*4+1][ra] = av.y; Ap[ka*4+2][ra] = av.z; Ap[ka*4+3][ra] = av.w;
    float4 nv = *(const float4*)(Aneg + (long)(m0 + ra) * D_ + k0 + ka * 4);
    An[ka*4+0][ra] = nv.x; An[ka*4+1][ra] = nv.y; An[ka*4+2][ra] = nv.z; An[ka*4+3][ra] = nv.w;
    *(float4*)&Bs[kb][nb*4] = *(const float4*)(Bm + (long)(k0 + kb) * HW_ + n0 + nb * 4);
    __syncthreads();
#pragma unroll
    for (int k = 0; k < 16; k++) {
      float4 ap = *(const float4*)&Ap[k][ty*4];
      float4 an = *(const float4*)&An[k][ty*4];
      ulonglong2 bb = *(const ulonglong2*)&Bs[k][tx*4];
      unsigned long long p0 = pk2(ap.x), p1 = pk2(ap.y), p2 = pk2(ap.z), p3 = pk2(ap.w);
      unsigned long long q0 = pk2(an.x), q1 = pk2(an.y), q2 = pk2(an.z), q3 = pk2(an.w);
      fma2(accP[0][0], p0, bb.x); fma2(accP[0][1], p0, bb.y);
      fma2(accP[1][0], p1, bb.x); fma2(accP[1][1], p1, bb.y);
      fma2(accP[2][0], p2, bb.x); fma2(accP[2][1], p2, bb.y);
      fma2(accP[3][0], p3, bb.x); fma2(accP[3][1], p3, bb.y);
      fma2(accN[0][0], q0, bb.x); fma2(accN[0][1], q0, bb.y);
      fma2(accN[1][0], q1, bb.x); fma2(accN[1][1], q1, bb.y);
      fma2(accN[2][0], q2, bb.x); fma2(accN[2][1], q2, bb.y);
      fma2(accN[3][0], q3, bb.x); fma2(accN[3][1], q3, bb.y);
    }
    __syncthreads();
  }

  float lsum = 0.f;
#pragma unroll
  for (int i = 0; i < 4; i++) {
    float2 pl = up2(accP[i][0]), ph = up2(accP[i][1]);
    float2 ql = up2(accN[i][0]), qh = up2(accN[i][1]);
    long idx = ((long)b * D_ + m0 + ty*4 + i) * HW_ + n0 + tx*4;
    float4 vs = *(const float4*)(Vs + idx);
    float4 o = make_float4(vs.x + pl.x, vs.y + pl.y, vs.z + ph.x, vs.w + ph.y);
    *(float4*)(out + idx) = o;
    lsum += fmaxf(ql.x - pl.x + 12.0f, 0.0f);
    lsum += fmaxf(ql.y - pl.y + 12.0f, 0.0f);
    lsum += fmaxf(qh.x - ph.x + 12.0f, 0.0f);
    lsum += fmaxf(qh.y - ph.y + 12.0f, 0.0f);
  }
  __shared__ float red[256];
  red[tid] = lsum;
  __syncthreads();
  for (int s = 128; s; s >>= 1) {
    if (tid < s) red[tid] += red[tid + s];
    __syncthreads();
  }
  if (tid == 0)
    g_part[blockIdx.z * (gridDim.x * gridDim.y) + blockIdx.x * gridDim.y + blockIdx.y] = red[0];
}

__global__ void __launch_bounds__(256) loss_reduce(float* __restrict__ out, int out_size)
{
  __shared__ float red[256];
  int tid = threadIdx.x;
  float s = 0.f;
  for (int i = tid; i < NPART; i += 256) s += g_part[i];
  red[tid] = s;
  __syncthreads();
  for (int st = 128; st; st >>= 1) {
    if (tid < st) red[tid] += red[tid + st];
    __syncthreads();
  }
  if (tid == 0 && (long)out_size > NOUT)
    out[NOUT] = red[0] / (float)(16.0 * 448.0 * 4096.0);
}

extern "C" void kernel_launch(void* const* d_in, const int* in_sizes, int n_in,
                              void* d_out, int out_size)
{
  (void)in_sizes; (void)n_in;
  const float* V_r = (const float*)d_in[0];
  const float* V_s = (const float*)d_in[1];
  const float* W_q = (const float*)d_in[2];
  const float* W_k = (const float*)d_in[3];
  const float* W_v = (const float*)d_in[4];
  float* out = (float*)d_out;

  cudaFuncSetAttribute(gram_mma_neg, cudaFuncAttributeMaxDynamicSharedMemorySize, MSMEM + 1024);

  dim3 blk(256);
  split_pair<<<512, blk>>>(V_s, g_VsH, g_VsL, BIG / 4);
  split_pair<<<512, blk>>>(V_r, g_VrH, g_VrL, BIG / 4);
  gram_pos    <<<dim3(7, 7, 16), blk>>>(V_s, V_r);              // pos gram: SIMT (output-0 path)
  gram_mma_neg<<<dim3(4, 4, 16), blk, MSMEM + 1024>>>();        // neg gram: MMA (loss-only path)
  gkt_kernel<<<dim3(7, 7, 32), blk>>>(W_k);
  wqt_kernel<<<dim3(7, 7, 32), blk>>>(W_q);
  softmax_kernel<<<1792,       blk>>>();
  av_kernel <<<dim3(7, 7, 32), blk>>>(W_v);
  final_kernel<<<dim3(7, 64, 16), blk>>>(V_r, V_s, out);
  loss_reduce <<<1,            blk>>>(out, out_size);
}

// round 13
// speedup vs baseline: 1.2991x; 1.2738x over previous
#include <cuda_runtime.h>

#define B_   16
#define D_   448
#define HW_  4096
#define DSQ  (D_*D_)
#define NOUT (16L*448L*4096L)
#define NPART 7168

__device__ float g_G[32L*DSQ];
__device__ float g_T[32L*DSQ];
__device__ float g_S[32L*DSQ];
__device__ float g_A[32L*DSQ];
__device__ float g_part[NPART];

__device__ __forceinline__ unsigned long long pk2(float v){
  unsigned long long r; asm("mov.b64 %0, {%1, %1};" : "=l"(r) : "f"(v)); return r;
}
__device__ __forceinline__ void fma2(unsigned long long &d, unsigned long long a, unsigned long long b){
  asm("fma.rn.f32x2 %0, %1, %2, %0;" : "+l"(d) : "l"(a), "l"(b));
}
__device__ __forceinline__ float2 up2(unsigned long long v){
  float2 f; asm("mov.b64 {%0, %1}, %2;" : "=f"(f.x), "=f"(f.y) : "l"(v)); return f;
}

// ---- 64x64 tile GEMM, 256 threads, 4x4/thread, BK=16 — R1 engine with PACKED-A smem ----
// A stored in smem pre-packed as {a,a} ull -> inner loop has no MOVs (issue-bound fix).
template<bool NT>
__device__ __forceinline__ void gemm_body(const float* __restrict__ A, const float* __restrict__ B,
                                          float* __restrict__ C, int K, int lda, int ldb, int ldc,
                                          float scale)
{
  __shared__ unsigned long long As[16][66];  // packed {a,a}
  __shared__ float Bs[16][68];
  const int tid = threadIdx.x;
  const int tx = tid & 15, ty = tid >> 4;
  const int m0 = blockIdx.x * 64, n0 = blockIdx.y * 64;
  unsigned long long acc[4][2];
#pragma unroll
  for (int i = 0; i < 4; i++) { acc[i][0] = 0ull; acc[i][1] = 0ull; }
  const int ra = tid >> 2, ka = tid & 3;
  const int kb = tid >> 4, nb = tid & 15;

  for (int k0 = 0; k0 < K; k0 += 16) {
    float4 av = *(const float4*)(A + (long)(m0 + ra) * lda + k0 + ka * 4);
    As[ka*4+0][ra] = pk2(av.x); As[ka*4+1][ra] = pk2(av.y);
    As[ka*4+2][ra] = pk2(av.z); As[ka*4+3][ra] = pk2(av.w);
    if (NT) {
      float4 bv = *(const float4*)(B + (long)(n0 + ra) * ldb + k0 + ka * 4);
      Bs[ka*4+0][ra] = bv.x; Bs[ka*4+1][ra] = bv.y; Bs[ka*4+2][ra] = bv.z; Bs[ka*4+3][ra] = bv.w;
    } else {
      *(float4*)&Bs[kb][nb*4] = *(const float4*)(B + (long)(k0 + kb) * ldb + n0 + nb * 4);
    }
    __syncthreads();
#pragma unroll
    for (int k = 0; k < 16; k++) {
      ulonglong2 a01 = *(const ulonglong2*)&As[k][ty*4];
      ulonglong2 a23 = *(const ulonglong2*)&As[k][ty*4 + 2];
      ulonglong2 bb  = *(const ulonglong2*)&Bs[k][tx*4];
      fma2(acc[0][0], a01.x, bb.x); fma2(acc[0][1], a01.x, bb.y);
      fma2(acc[1][0], a01.y, bb.x); fma2(acc[1][1], a01.y, bb.y);
      fma2(acc[2][0], a23.x, bb.x); fma2(acc[2][1], a23.x, bb.y);
      fma2(acc[3][0], a23.y, bb.x); fma2(acc[3][1], a23.y, bb.y);
    }
    __syncthreads();
  }
#pragma unroll
  for (int i = 0; i < 4; i++) {
    float2 lo = up2(acc[i][0]), hi = up2(acc[i][1]);
    float4 o = make_float4(lo.x*scale, lo.y*scale, hi.x*scale, hi.y*scale);
    *(float4*)(C + (long)(m0 + ty*4 + i) * ldc + n0 + tx*4) = o;
  }
}

__global__ void __launch_bounds__(256) gram_kernel(const float* __restrict__ Vs,
                                                   const float* __restrict__ Vr)
{
  int z = blockIdx.z;
  int b = z & 15;
  int b2 = (z < 16) ? b : ((b + 1) & 15);
  gemm_body<true>(Vs + (long)b  * D_ * HW_,
                  Vr + (long)b2 * D_ * HW_,
                  g_G + (long)z * DSQ, HW_, HW_, HW_, D_, 1.0f);
}

__global__ void __launch_bounds__(256) gkt_kernel(const float* __restrict__ Wk)
{
  int z = blockIdx.z;
  gemm_body<true>(g_G + (long)z * DSQ, Wk, g_T + (long)z * DSQ, D_, D_, D_, D_, 1.0f);
}

__global__ void __launch_bounds__(256) wqt_kernel(const float* __restrict__ Wq)
{
  int z = blockIdx.z;
  const float SCALE = 0.047245559f; // 1/sqrt(448)
  gemm_body<false>(Wq, g_T + (long)z * DSQ, g_S + (long)z * DSQ, D_, D_, D_, D_, SCALE);
}

__global__ void __launch_bounds__(256) softmax_kernel()
{
  int warp = (blockIdx.x * blockDim.x + threadIdx.x) >> 5;
  int lane = threadIdx.x & 31;
  if (warp >= 32 * D_) return;
  float* row = g_S + (long)warp * D_;
  float v[14];
  float mx = -1e30f;
#pragma unroll
  for (int i = 0; i < 14; i++) { v[i] = row[lane + i * 32]; mx = fmaxf(mx, v[i]); }
#pragma unroll
  for (int o = 16; o; o >>= 1) mx = fmaxf(mx, __shfl_xor_sync(0xffffffffu, mx, o));
  float s = 0.f;
#pragma unroll
  for (int i = 0; i < 14; i++) { v[i] = __expf(v[i] - mx); s += v[i]; }
#pragma unroll
  for (int o = 16; o; o >>= 1) s += __shfl_xor_sync(0xffffffffu, s, o);
  float inv = 1.0f / s;
#pragma unroll
  for (int i = 0; i < 14; i++) row[lane + i * 32] = v[i] * inv;
}

__global__ void __launch_bounds__(256) av_kernel(const float* __restrict__ Wv)
{
  int z = blockIdx.z;
  gemm_body<false>(g_S + (long)z * DSQ, Wv, g_A + (long)z * DSQ, D_, D_, D_, D_, 1.0f);
}

// dual-GEMM final with packed Ap/An smem (same math as R1)
__global__ void __launch_bounds__(256) final_kernel(const float* __restrict__ Vr,
                                                    const float* __restrict__ Vs,
                                                    float* __restrict__ out)
{
  __shared__ unsigned long long Ap[16][66];
  __shared__ unsigned long long An[16][66];
  __shared__ float Bs[16][68];
  const int b = blockIdx.z;
  const float* Apos = g_A + (long)b * DSQ;
  const float* Aneg = g_A + (long)(16 + b) * DSQ;
  const float* Bm   = Vr + (long)b * D_ * HW_;
  const int tid = threadIdx.x;
  const int tx = tid & 15, ty = tid >> 4;
  const int m0 = blockIdx.x * 64, n0 = blockIdx.y * 64;
  unsigned long long accP[4][2], accN[4][2];
#pragma unroll
  for (int i = 0; i < 4; i++) { accP[i][0]=0ull; accP[i][1]=0ull; accN[i][0]=0ull; accN[i][1]=0ull; }
  const int ra = tid >> 2, ka = tid & 3;
  const int kb = tid >> 4, nb = tid & 15;

  for (int k0 = 0; k0 < D_; k0 += 16) {
    float4 av = *(const float4*)(Apos + (long)(m0 + ra) * D_ + k0 + ka * 4);
    Ap[ka*4+0][ra] = pk2(av.x); Ap[ka*4+1][ra] = pk2(av.y);
    Ap[ka*4+2][ra] = pk2(av.z); Ap[ka*4+3][ra] = pk2(av.w);
    float4 nv = *(const float4*)(Aneg + (long)(m0 + ra) * D_ + k0 + ka * 4);
    An[ka*4+0][ra] = pk2(nv.x); An[ka*4+1][ra] = pk2(nv.y);
    An[ka*4+2][ra] = pk2(nv.z); An[ka*4+3][ra] = pk2(nv.w);
    *(float4*)&Bs[kb][nb*4] = *(const float4*)(Bm + (long)(k0 + kb) * HW_ + n0 + nb * 4);
    __syncthreads();
#pragma unroll
    for (int k = 0; k < 16; k++) {
      ulonglong2 p01 = *(const ulonglong2*)&Ap[k][ty*4];
      ulonglong2 p23 = *(const ulonglong2*)&Ap[k][ty*4 + 2];
      ulonglong2 q01 = *(const ulonglong2*)&An[k][ty*4];
      ulonglong2 q23 = *(const ulonglong2*)&An[k][ty*4 + 2];
      ulonglong2 bb  = *(const ulonglong2*)&Bs[k][tx*4];
      fma2(accP[0][0], p01.x, bb.x); fma2(accP[0][1], p01.x, bb.y);
      fma2(accP[1][0], p01.y, bb.x); fma2(accP[1][1], p01.y, bb.y);
      fma2(accP[2][0], p23.x, bb.x); fma2(accP[2][1], p23.x, bb.y);
      fma2(accP[3][0], p23.y, bb.x); fma2(accP[3][1], p23.y, bb.y);
      fma2(accN[0][0], q01.x, bb.x); fma2(accN[0][1], q01.x, bb.y);
      fma2(accN[1][0], q01.y, bb.x); fma2(accN[1][1], q01.y, bb.y);
      fma2(accN[2][0], q23.x, bb.x); fma2(accN[2][1], q23.x, bb.y);
      fma2(accN[3][0], q23.y, bb.x); fma2(accN[3][1], q23.y, bb.y);
    }
    __syncthreads();
  }

  float lsum = 0.f;
#pragma unroll
  for (int i = 0; i < 4; i++) {
    float2 pl = up2(accP[i][0]), ph = up2(accP[i][1]);
    float2 ql = up2(accN[i][0]), qh = up2(accN[i][1]);
    long idx = ((long)b * D_ + m0 + ty*4 + i) * HW_ + n0 + tx*4;
    float4 vs = *(const float4*)(Vs + idx);
    float4 o = make_float4(vs.x + pl.x, vs.y + pl.y, vs.z + ph.x, vs.w + ph.y);
    *(float4*)(out + idx) = o;
    lsum += fmaxf(ql.x - pl.x + 12.0f, 0.0f);
    lsum += fmaxf(ql.y - pl.y + 12.0f, 0.0f);
    lsum += fmaxf(qh.x - ph.x + 12.0f, 0.0f);
    lsum += fmaxf(qh.y - ph.y + 12.0f, 0.0f);
  }
  __shared__ float red[256];
  red[tid] = lsum;
  __syncthreads();
  for (int s = 128; s; s >>= 1) {
    if (tid < s) red[tid] += red[tid + s];
    __syncthreads();
  }
  if (tid == 0)
    g_part[blockIdx.z * (gridDim.x * gridDim.y) + blockIdx.x * gridDim.y + blockIdx.y] = red[0];
}

__global__ void __launch_bounds__(256) loss_reduce(float* __restrict__ out, int out_size)
{
  __shared__ float red[256];
  int tid = threadIdx.x;
  float s = 0.f;
  for (int i = tid; i < NPART; i += 256) s += g_part[i];
  red[tid] = s;
  __syncthreads();
  for (int st = 128; st; st >>= 1) {
    if (tid < st) red[tid] += red[tid + st];
    __syncthreads();
  }
  if (tid == 0 && (long)out_size > NOUT)
    out[NOUT] = red[0] / (float)(16.0 * 448.0 * 4096.0);
}

extern "C" void kernel_launch(void* const* d_in, const int* in_sizes, int n_in,
                              void* d_out, int out_size)
{
  (void)in_sizes; (void)n_in;
  const float* V_r = (const float*)d_in[0];
  const float* V_s = (const float*)d_in[1];
  const float* W_q = (const float*)d_in[2];
  const float* W_k = (const float*)d_in[3];
  const float* W_v = (const float*)d_in[4];
  float* out = (float*)d_out;

  dim3 blk(256);
  gram_kernel  <<<dim3(7, 7, 32),  blk>>>(V_s, V_r);
  gkt_kernel   <<<dim3(7, 7, 32),  blk>>>(W_k);
  wqt_kernel   <<<dim3(7, 7, 32),  blk>>>(W_q);
  softmax_kernel<<<1792,           blk>>>();
  av_kernel    <<<dim3(7, 7, 32),  blk>>>(W_v);
  final_kernel <<<dim3(7, 64, 16), blk>>>(V_r, V_s, out);
  loss_reduce  <<<1,               blk>>>(out, out_size);
}

// round 16
// speedup vs baseline: 2.0777x; 1.5994x over previous
#include <cuda_runtime.h>
#include <cuda_bf16.h>
typedef __nv_bfloat16 bf;

#define B_   16
#define D_   448
#define HW_  4096
#define DSQ  (D_*D_)
#define BIG  (16L*D_*HW_)
#define NOUT (16L*448L*4096L)
#define NPART 7168
#define MSMEM (65536 + 1024)

__device__ alignas(16) bf g_VsH[BIG], g_VsL[BIG], g_VrH[BIG], g_VrL[BIG];
__device__ float g_G[32L*DSQ];
__device__ float g_T[32L*DSQ];
__device__ float g_S[32L*DSQ];
__device__ float g_A[32L*DSQ];
__device__ float g_part[NPART];

// ---- packed fp32x2 helpers (validated R1) ----
__device__ __forceinline__ unsigned long long pk2(float v){
  unsigned long long r; asm("mov.b64 %0, {%1, %1};" : "=l"(r) : "f"(v)); return r;
}
__device__ __forceinline__ void fma2(unsigned long long &d, unsigned long long a, unsigned long long b){
  asm("fma.rn.f32x2 %0, %1, %2, %0;" : "+l"(d) : "l"(a), "l"(b));
}
__device__ __forceinline__ float2 up2(unsigned long long v){
  float2 f; asm("mov.b64 {%0, %1}, %2;" : "=f"(f.x), "=f"(f.y) : "l"(v)); return f;
}

// ---- mma helpers (R9 engine) ----
__device__ __forceinline__ unsigned su32(const void* p){ return (unsigned)__cvta_generic_to_shared(p); }
__device__ __forceinline__ void ldsm4(unsigned* r, unsigned a){
  asm volatile("ldmatrix.sync.aligned.m8n8.x4.shared.b16 {%0,%1,%2,%3}, [%4];"
    : "=r"(r[0]),"=r"(r[1]),"=r"(r[2]),"=r"(r[3]) : "r"(a));
}
__device__ __forceinline__ void mma16816(float* c, const unsigned* a, unsigned b0, unsigned b1){
  asm volatile("mma.sync.aligned.m16n8k16.row.col.f32.bf16.bf16.f32 "
    "{%0,%1,%2,%3}, {%4,%5,%6,%7}, {%8,%9}, {%0,%1,%2,%3};"
    : "+f"(c[0]),"+f"(c[1]),"+f"(c[2]),"+f"(c[3])
    : "r"(a[0]),"r"(a[1]),"r"(a[2]),"r"(a[3]), "r"(b0),"r"(b1));
}
__device__ __forceinline__ unsigned sw(unsigned off){ return off ^ ((off >> 3) & 0x70u); }

// ---- bf16 hi/lo split: device-side body; kernels reference the GLOBALS IN DEVICE CODE ----
// (R15 root cause: passing __device__ symbols as kernel args from host passes the
//  host shadow address; on GB300/ATS the writes silently land in HOST memory.)
__device__ __forceinline__ void split_body(const float* __restrict__ s,
                                           bf* __restrict__ h, bf* __restrict__ l, long n4)
{
  for (long i = blockIdx.x * 256L + threadIdx.x; i < n4; i += (long)gridDim.x * 256L){
    float4 x = ((const float4*)s)[i];
    bf h0=__float2bfloat16(x.x), h1=__float2bfloat16(x.y), h2=__float2bfloat16(x.z), h3=__float2bfloat16(x.w);
    __nv_bfloat162 a, bq; a.x=h0; a.y=h1; bq.x=h2; bq.y=h3;
    ((__nv_bfloat162*)h)[2*i] = a; ((__nv_bfloat162*)h)[2*i+1] = bq;
    __nv_bfloat162 cc, dd;
    cc.x=__float2bfloat16(x.x-__bfloat162float(h0)); cc.y=__float2bfloat16(x.y-__bfloat162float(h1));
    dd.x=__float2bfloat16(x.z-__bfloat162float(h2)); dd.y=__float2bfloat16(x.w-__bfloat162float(h3));
    ((__nv_bfloat162*)l)[2*i] = cc; ((__nv_bfloat162*)l)[2*i+1] = dd;
  }
}
__global__ void __launch_bounds__(256) split_Vs(const float* __restrict__ s){
  split_body(s, g_VsH, g_VsL, BIG / 4);
}
__global__ void __launch_bounds__(256) split_Vr(const float* __restrict__ s){
  split_body(s, g_VrH, g_VrL, BIG / 4);
}

// ---- mma gram, ALL 32 slices: G[z] = (VsH+VsL)[b] @ (VrH+VrL)[b2]^T (R9 engine) ----
__global__ void __launch_bounds__(256) gram_mma()
{
  extern __shared__ char raw[];
  unsigned rbase = su32(raw);
  char* dsm = raw + (((rbase + 1023u) & ~1023u) - rbase);
  const int tid = threadIdx.x, lane = tid & 31, wid = tid >> 5;
  const int wm = wid >> 2, wn = wid & 3;
  const int z = blockIdx.z;
  const int b = z & 15, b2 = (z < 16) ? b : ((b + 1) & 15);
  const int m0 = blockIdx.x * 128, n0 = blockIdx.y * 128;
  const bf* Ah = g_VsH + (long)b  * D_ * HW_;
  const bf* Al = g_VsL + (long)b  * D_ * HW_;
  const bf* Bh = g_VrH + (long)b2 * D_ * HW_;
  const bf* Bl = g_VrL + (long)b2 * D_ * HW_;

  float acc[4][4][4];
#pragma unroll
  for (int mi = 0; mi < 4; ++mi)
#pragma unroll
    for (int ni = 0; ni < 4; ++ni)
#pragma unroll
      for (int q = 0; q < 4; ++q) acc[mi][ni][q] = 0.f;

  unsigned sb = su32(dsm);
  for (int c = 0; c < 64; ++c){
    int k0 = c << 6;
    __syncthreads();
#pragma unroll
    for (int j = 0; j < 4; ++j){
      int i = tid + j * 256;
      int r = i >> 3, v = i & 7;
      unsigned off = sw((unsigned)(r * 128 + v * 16));
      int ra = m0 + r; if (ra > D_ - 1) ra = D_ - 1;
      long ea = (long)ra * HW_ + k0 + v * 8;
      *(uint4*)(dsm + off)         = *(const uint4*)(Ah + ea);
      *(uint4*)(dsm + 16384 + off) = *(const uint4*)(Al + ea);
      int rb = n0 + r; if (rb > D_ - 1) rb = D_ - 1;
      long eb = (long)rb * HW_ + k0 + v * 8;
      *(uint4*)(dsm + 32768 + off) = *(const uint4*)(Bh + eb);
      *(uint4*)(dsm + 49152 + off) = *(const uint4*)(Bl + eb);
    }
    __syncthreads();
#pragma unroll
    for (int k16 = 0; k16 < 4; ++k16){
      unsigned ah[4][4], al[4][4], bh[2][4], bl[2][4];
      unsigned cb = (unsigned)(k16 * 32 + ((lane >> 4) << 4));
#pragma unroll
      for (int mi = 0; mi < 4; ++mi){
        unsigned off = sw((unsigned)((wm * 64 + mi * 16 + (lane & 15)) * 128 + cb));
        ldsm4(ah[mi], sb + off);
        ldsm4(al[mi], sb + 16384 + off);
      }
#pragma unroll
      for (int nb = 0; nb < 2; ++nb){
        unsigned off = sw((unsigned)((wn * 32 + nb * 16 + ((lane >> 3) & 1) * 8 + (lane & 7)) * 128 + cb));
        ldsm4(bh[nb], sb + 32768 + off);
        ldsm4(bl[nb], sb + 49152 + off);
      }
#pragma unroll
      for (int mi = 0; mi < 4; ++mi)
#pragma unroll
        for (int ni = 0; ni < 4; ++ni){
          int nb = ni >> 1, sel = ni & 1;
          float* cc = acc[mi][ni];
          mma16816(cc, ah[mi], bh[nb][sel], bh[nb][sel + 2]);
          mma16816(cc, ah[mi], bl[nb][sel], bl[nb][sel + 2]);
          mma16816(cc, al[mi], bh[nb][sel], bh[nb][sel + 2]);
        }
    }
  }

  float* Cg = g_G + (long)z * DSQ;
#pragma unroll
  for (int mi = 0; mi < 4; ++mi)
#pragma unroll
    for (int ni = 0; ni < 4; ++ni){
      float* c = acc[mi][ni];
      int r = m0 + wm * 64 + mi * 16 + (lane >> 2);
      int n = n0 + wn * 32 + ni * 8 + ((lane & 3) << 1);
      if (n < D_){
        if (r < D_)     *(float2*)(Cg + (long)r * D_ + n)       = make_float2(c[0], c[1]);
        if (r + 8 < D_) *(float2*)(Cg + (long)(r + 8) * D_ + n) = make_float2(c[2], c[3]);
      }
    }
}

// ================= R1 known-good SIMT chain (verbatim) =================
template<bool NT>
__device__ __forceinline__ void gemm_body(const float* __restrict__ A, const float* __restrict__ B,
                                          float* __restrict__ C, int K, int lda, int ldb, int ldc,
                                          float scale)
{
  __shared__ float As[16][68];
  __shared__ float Bs[16][68];
  const int tid = threadIdx.x;
  const int tx = tid & 15, ty = tid >> 4;
  const int m0 = blockIdx.x * 64, n0 = blockIdx.y * 64;
  unsigned long long acc[4][2];
#pragma unroll
  for (int i = 0; i < 4; i++) { acc[i][0] = 0ull; acc[i][1] = 0ull; }
  const int ra = tid >> 2, ka = tid & 3;
  const int kb = tid >> 4, nb = tid & 15;

  for (int k0 = 0; k0 < K; k0 += 16) {
    float4 av = *(const float4*)(A + (long)(m0 + ra) * lda + k0 + ka * 4);
    As[ka*4+0][ra] = av.x; As[ka*4+1][ra] = av.y; As[ka*4+2][ra] = av.z; As[ka*4+3][ra] = av.w;
    if (NT) {
      float4 bv = *(const float4*)(B + (long)(n0 + ra) * ldb + k0 + ka * 4);
      Bs[ka*4+0][ra] = bv.x; Bs[ka*4+1][ra] = bv.y; Bs[ka*4+2][ra] = bv.z; Bs[ka*4+3][ra] = bv.w;
    } else {
      *(float4*)&Bs[kb][nb*4] = *(const float4*)(B + (long)(k0 + kb) * ldb + n0 + nb * 4);
    }
    __syncthreads();
#pragma unroll
    for (int k = 0; k < 16; k++) {
      float4 a = *(const float4*)&As[k][ty*4];
      ulonglong2 bb = *(const ulonglong2*)&Bs[k][tx*4];
      unsigned long long a0 = pk2(a.x), a1 = pk2(a.y), a2 = pk2(a.z), a3 = pk2(a.w);
      fma2(acc[0][0], a0, bb.x); fma2(acc[0][1], a0, bb.y);
      fma2(acc[1][0], a1, bb.x); fma2(acc[1][1], a1, bb.y);
      fma2(acc[2][0], a2, bb.x); fma2(acc[2][1], a2, bb.y);
      fma2(acc[3][0], a3, bb.x); fma2(acc[3][1], a3, bb.y);
    }
    __syncthreads();
  }
#pragma unroll
  for (int i = 0; i < 4; i++) {
    float2 lo = up2(acc[i][0]), hi = up2(acc[i][1]);
    float4 o = make_float4(lo.x*scale, lo.y*scale, hi.x*scale, hi.y*scale);
    *(float4*)(C + (long)(m0 + ty*4 + i) * ldc + n0 + tx*4) = o;
  }
}

__global__ void __launch_bounds__(256) gkt_kernel(const float* __restrict__ Wk)
{
  int z = blockIdx.z;
  gemm_body<true>(g_G + (long)z * DSQ, Wk, g_T + (long)z * DSQ, D_, D_, D_, D_, 1.0f);
}

__global__ void __launch_bounds__(256) wqt_kernel(const float* __restrict__ Wq)
{
  int z = blockIdx.z;
  const float SCALE = 0.047245559f;
  gemm_body<false>(Wq, g_T + (long)z * DSQ, g_S + (long)z * DSQ, D_, D_, D_, D_, SCALE);
}

__global__ void __launch_bounds__(256) softmax_kernel()
{
  int warp = (blockIdx.x * blockDim.x + threadIdx.x) >> 5;
  int lane = threadIdx.x & 31;
  if (warp >= 32 * D_) return;
  float* row = g_S + (long)warp * D_;
  float v[14];
  float mx = -1e30f;
#pragma unroll
  for (int i = 0; i < 14; i++) { v[i] = row[lane + i * 32]; mx = fmaxf(mx, v[i]); }
#pragma unroll
  for (int o = 16; o; o >>= 1) mx = fmaxf(mx, __shfl_xor_sync(0xffffffffu, mx, o));
  float s = 0.f;
#pragma unroll
  for (int i = 0; i < 14; i++) { v[i] = __expf(v[i] - mx); s += v[i]; }
#pragma unroll
  for (int o = 16; o; o >>= 1) s += __shfl_xor_sync(0xffffffffu, s, o);
  float inv = 1.0f / s;
#pragma unroll
  for (int i = 0; i < 14; i++) row[lane + i * 32] = v[i] * inv;
}

__global__ void __launch_bounds__(256) av_kernel(const float* __restrict__ Wv)
{
  int z = blockIdx.z;
  gemm_body<false>(g_S + (long)z * DSQ, Wv, g_A + (long)z * DSQ, D_, D_, D_, D_, 1.0f);
}

__global__ void __launch_bounds__(256) final_kernel(const float* __restrict__ Vr,
                                                    const float* __restrict__ Vs,
                                                    float* __restrict__ out)
{
  __shared__ float Ap[16][68];
  __shared__ float An[16][68];
  __shared__ float Bs[16][68];
  const int b = blockIdx.z;
  const float* Apos = g_A + (long)b * DSQ;
  const float* Aneg = g_A + (long)(16 + b) * DSQ;
  const float* Bm   = Vr + (long)b * D_ * HW_;
  const int tid = threadIdx.x;
  const int tx = tid & 15, ty = tid >> 4;
  const int m0 = blockIdx.x * 64, n0 = blockIdx.y * 64;
  unsigned long long accP[4][2], accN[4][2];
#pragma unroll
  for (int i = 0; i < 4; i++) { accP[i][0]=0ull; accP[i][1]=0ull; accN[i][0]=0ull; accN[i][1]=0ull; }
  const int ra = tid >> 2, ka = tid & 3;
  const int kb = tid >> 4, nb = tid & 15;

  for (int k0 = 0; k0 < D_; k0 += 16) {
    float4 av = *(const float4*)(Apos + (long)(m0 + ra) * D_ + k0 + ka * 4);
    Ap[ka*4+0][ra] = av.x; Ap[ka*4+1][ra] = av.y; Ap[ka*4+2][ra] = av.z; Ap[ka*4+3][ra] = av.w;
    float4 nv = *(const float4*)(Aneg + (long)(m0 + ra) * D_ + k0 + ka * 4);
    An[ka*4+0][ra] = nv.x; An[ka*4+1][ra] = nv.y; An[ka*4+2][ra] = nv.z; An[ka*4+3][ra] = nv.w;
    *(float4*)&Bs[kb][nb*4] = *(const float4*)(Bm + (long)(k0 + kb) * HW_ + n0 + nb * 4);
    __syncthreads();
#pragma unroll
    for (int k = 0; k < 16; k++) {
      float4 ap = *(const float4*)&Ap[k][ty*4];
      float4 an = *(const float4*)&An[k][ty*4];
      ulonglong2 bb = *(const ulonglong2*)&Bs[k][tx*4];
      unsigned long long p0 = pk2(ap.x), p1 = pk2(ap.y), p2 = pk2(ap.z), p3 = pk2(ap.w);
      unsigned long long q0 = pk2(an.x), q1 = pk2(an.y), q2 = pk2(an.z), q3 = pk2(an.w);
      fma2(accP[0][0], p0, bb.x); fma2(accP[0][1], p0, bb.y);
      fma2(accP[1][0], p1, bb.x); fma2(accP[1][1], p1, bb.y);
      fma2(accP[2][0], p2, bb.x); fma2(accP[2][1], p2, bb.y);
      fma2(accP[3][0], p3, bb.x); fma2(accP[3][1], p3, bb.y);
      fma2(accN[0][0], q0, bb.x); fma2(accN[0][1], q0, bb.y);
      fma2(accN[1][0], q1, bb.x); fma2(accN[1][1], q1, bb.y);
      fma2(accN[2][0], q2, bb.x); fma2(accN[2][1], q2, bb.y);
      fma2(accN[3][0], q3, bb.x); fma2(accN[3][1], q3, bb.y);
    }
    __syncthreads();
  }

  float lsum = 0.f;
#pragma unroll
  for (int i = 0; i < 4; i++) {
    float2 pl = up2(accP[i][0]), ph = up2(accP[i][1]);
    float2 ql = up2(accN[i][0]), qh = up2(accN[i][1]);
    long idx = ((long)b * D_ + m0 + ty*4 + i) * HW_ + n0 + tx*4;
    float4 vs = *(const float4*)(Vs + idx);
    float4 o = make_float4(vs.x + pl.x, vs.y + pl.y, vs.z + ph.x, vs.w + ph.y);
    *(float4*)(out + idx) = o;
    lsum += fmaxf(ql.x - pl.x + 12.0f, 0.0f);
    lsum += fmaxf(ql.y - pl.y + 12.0f, 0.0f);
    lsum += fmaxf(qh.x - ph.x + 12.0f, 0.0f);
    lsum += fmaxf(qh.y - ph.y + 12.0f, 0.0f);
  }
  __shared__ float red[256];
  red[tid] = lsum;
  __syncthreads();
  for (int s = 128; s; s >>= 1) {
    if (tid < s) red[tid] += red[tid + s];
    __syncthreads();
  }
  if (tid == 0)
    g_part[blockIdx.z * (gridDim.x * gridDim.y) + blockIdx.x * gridDim.y + blockIdx.y] = red[0];
}

__global__ void __launch_bounds__(256) loss_reduce(float* __restrict__ out, int out_size)
{
  __shared__ float red[256];
  int tid = threadIdx.x;
  float s = 0.f;
  for (int i = tid; i < NPART; i += 256) s += g_part[i];
  red[tid] = s;
  __syncthreads();
  for (int st = 128; st; st >>= 1) {
    if (tid < st) red[tid] += red[tid + st];
    __syncthreads();
  }
  if (tid == 0 && (long)out_size > NOUT)
    out[NOUT] = red[0] / (float)(16.0 * 448.0 * 4096.0);
}

extern "C" void kernel_launch(void* const* d_in, const int* in_sizes, int n_in,
                              void* d_out, int out_size)
{
  (void)in_sizes; (void)n_in;
  const float* V_r = (const float*)d_in[0];
  const float* V_s = (const float*)d_in[1];
  const float* W_q = (const float*)d_in[2];
  const float* W_k = (const float*)d_in[3];
  const float* W_v = (const float*)d_in[4];
  float* out = (float*)d_out;

  cudaFuncSetAttribute(gram_mma, cudaFuncAttributeMaxDynamicSharedMemorySize, MSMEM);

  dim3 blk(256);
  split_Vs<<<512, blk>>>(V_s);                        // device-symbol targets (R15 fix)
  split_Vr<<<512, blk>>>(V_r);
  gram_mma  <<<dim3(4, 4, 32), blk, MSMEM>>>();       // G (all 32) via tensor cores
  gkt_kernel<<<dim3(7, 7, 32), blk>>>(W_k);
  wqt_kernel<<<dim3(7, 7, 32), blk>>>(W_q);
  softmax_kernel<<<1792,       blk>>>();
  av_kernel <<<dim3(7, 7, 32), blk>>>(W_v);
  final_kernel<<<dim3(7, 64, 16), blk>>>(V_r, V_s, out);
  loss_reduce <<<1,            blk>>>(out, out_size);
}

// round 17
// speedup vs baseline: 2.8412x; 1.3675x over previous
#include <cuda_runtime.h>
#include <cuda_bf16.h>
typedef __nv_bfloat16 bf;

#define B_   16
#define D_   448
#define HW_  4096
#define DSQ  (D_*D_)
#define BIG  (16L*D_*HW_)
#define NOUT (16L*448L*4096L)
#define NLOSS 1024
#define STAGE 65536
#define MSMEM (2*STAGE + 1024)

__device__ alignas(16) bf g_VsH[BIG], g_VsL[BIG], g_VrH[BIG], g_VrL[BIG];
__device__ alignas(16) bf g_VtH[BIG], g_VtL[BIG];        // Vr^T per batch [hw][c]
__device__ alignas(16) bf g_AH[32L*DSQ], g_AL[32L*DSQ];  // split of A'
__device__ float g_G[32L*DSQ];
__device__ float g_T[32L*DSQ];
__device__ float g_S[32L*DSQ];
__device__ float g_A[32L*DSQ];
__device__ float g_neg[BIG];
__device__ float g_part[NLOSS];

// ---- packed fp32x2 helpers (validated) ----
__device__ __forceinline__ unsigned long long pk2(float v){
  unsigned long long r; asm("mov.b64 %0, {%1, %1};" : "=l"(r) : "f"(v)); return r;
}
__device__ __forceinline__ void fma2(unsigned long long &d, unsigned long long a, unsigned long long b){
  asm("fma.rn.f32x2 %0, %1, %2, %0;" : "+l"(d) : "l"(a), "l"(b));
}
__device__ __forceinline__ float2 up2(unsigned long long v){
  float2 f; asm("mov.b64 {%0, %1}, %2;" : "=f"(f.x), "=f"(f.y) : "l"(v)); return f;
}

// ---- mma / cp.async helpers ----
__device__ __forceinline__ unsigned su32(const void* p){ return (unsigned)__cvta_generic_to_shared(p); }
__device__ __forceinline__ void cpa16(unsigned d, const void* s){
  asm volatile("cp.async.cg.shared.global [%0], [%1], 16;" :: "r"(d), "l"(s));
}
__device__ __forceinline__ void cpc(){ asm volatile("cp.async.commit_group;" ::: "memory"); }
template<int N> __device__ __forceinline__ void cpw(){
  asm volatile("cp.async.wait_group %0;" :: "n"(N) : "memory");
}
__device__ __forceinline__ void ldsm4(unsigned* r, unsigned a){
  asm volatile("ldmatrix.sync.aligned.m8n8.x4.shared.b16 {%0,%1,%2,%3}, [%4];"
    : "=r"(r[0]),"=r"(r[1]),"=r"(r[2]),"=r"(r[3]) : "r"(a));
}
__device__ __forceinline__ void mma16816(float* c, const unsigned* a, unsigned b0, unsigned b1){
  asm volatile("mma.sync.aligned.m16n8k16.row.col.f32.bf16.bf16.f32 "
    "{%0,%1,%2,%3}, {%4,%5,%6,%7}, {%8,%9}, {%0,%1,%2,%3};"
    : "+f"(c[0]),"+f"(c[1]),"+f"(c[2]),"+f"(c[3])
    : "r"(a[0]),"r"(a[1]),"r"(a[2]),"r"(a[3]), "r"(b0),"r"(b1));
}
__device__ __forceinline__ unsigned sw(unsigned off){ return off ^ ((off >> 3) & 0x70u); }

// ---- splits: globals referenced IN DEVICE CODE (R15 lesson) ----
__device__ __forceinline__ void split_body(const float* __restrict__ s,
                                           bf* __restrict__ h, bf* __restrict__ l, long n4)
{
  for (long i = blockIdx.x * 256L + threadIdx.x; i < n4; i += (long)gridDim.x * 256L){
    float4 x = ((const float4*)s)[i];
    bf h0=__float2bfloat16(x.x), h1=__float2bfloat16(x.y), h2=__float2bfloat16(x.z), h3=__float2bfloat16(x.w);
    __nv_bfloat162 a, bq; a.x=h0; a.y=h1; bq.x=h2; bq.y=h3;
    ((__nv_bfloat162*)h)[2*i] = a; ((__nv_bfloat162*)h)[2*i+1] = bq;
    __nv_bfloat162 cc, dd;
    cc.x=__float2bfloat16(x.x-__bfloat162float(h0)); cc.y=__float2bfloat16(x.y-__bfloat162float(h1));
    dd.x=__float2bfloat16(x.z-__bfloat162float(h2)); dd.y=__float2bfloat16(x.w-__bfloat162float(h3));
    ((__nv_bfloat162*)l)[2*i] = cc; ((__nv_bfloat162*)l)[2*i+1] = dd;
  }
}
__global__ void __launch_bounds__(256) split_Vs(const float* __restrict__ s){ split_body(s, g_VsH, g_VsL, BIG/4); }
__global__ void __launch_bounds__(256) split_Vr(const float* __restrict__ s){ split_body(s, g_VrH, g_VrL, BIG/4); }
__global__ void __launch_bounds__(256) split_A (){ split_body(g_A, g_AH, g_AL, 32L*DSQ/4); }

// ---- transpose+split Vr -> VtH/VtL [hw][c] ----
__global__ void __launch_bounds__(256) trans_split(const float* __restrict__ Vr)
{
  __shared__ float t[32][33];
  int b = blockIdx.z, h0 = blockIdx.x * 32, c0 = blockIdx.y * 32;
  int tx = threadIdx.x, ty = threadIdx.y;
  const float* src = Vr + (long)b * D_ * HW_;
#pragma unroll
  for (int i = 0; i < 4; ++i) t[ty + 8*i][tx] = src[(long)(c0 + ty + 8*i) * HW_ + h0 + tx];
  __syncthreads();
  bf* th = g_VtH + (long)b * HW_ * D_;
  bf* tl = g_VtL + (long)b * HW_ * D_;
#pragma unroll
  for (int i = 0; i < 4; ++i){
    float x = t[tx][ty + 8*i];
    bf hh = __float2bfloat16(x);
    long o = (long)(h0 + ty + 8*i) * D_ + c0 + tx;
    th[o] = hh; tl[o] = __float2bfloat16(x - __bfloat162float(hh));
  }
}

// ---- cp.async double-buffered mainloop compute section (shared by gram/final) ----
__device__ __forceinline__ void mma_chunk(unsigned st, int lane, int wm, int wn, float acc[4][4][4])
{
#pragma unroll
  for (int k16 = 0; k16 < 4; ++k16){
    unsigned ah[4][4], al[4][4], bh[2][4], bl[2][4];
    unsigned cb = (unsigned)(k16 * 32 + ((lane >> 4) << 4));
#pragma unroll
    for (int mi = 0; mi < 4; ++mi){
      unsigned off = sw((unsigned)((wm * 64 + mi * 16 + (lane & 15)) * 128 + cb));
      ldsm4(ah[mi], st + off);
      ldsm4(al[mi], st + 16384 + off);
    }
#pragma unroll
    for (int nb = 0; nb < 2; ++nb){
      unsigned off = sw((unsigned)((wn * 32 + nb * 16 + ((lane >> 3) & 1) * 8 + (lane & 7)) * 128 + cb));
      ldsm4(bh[nb], st + 32768 + off);
      ldsm4(bl[nb], st + 49152 + off);
    }
#pragma unroll
    for (int mi = 0; mi < 4; ++mi)
#pragma unroll
      for (int ni = 0; ni < 4; ++ni){
        int nb = ni >> 1, sel = ni & 1;
        float* cc = acc[mi][ni];
        mma16816(cc, ah[mi], bh[nb][sel], bh[nb][sel + 2]);
        mma16816(cc, ah[mi], bl[nb][sel], bl[nb][sel + 2]);
        mma16816(cc, al[mi], bh[nb][sel], bh[nb][sel + 2]);
      }
  }
}

// ---- gram (cp.async): G[z] = (VsH+VsL)[b] @ (VrH+VrL)[b2]^T ----
__device__ __forceinline__ void fill_gram(unsigned st,
    const bf* Ah, const bf* Al, const bf* Bh, const bf* Bl,
    int m0, int n0, int k0, int tid)
{
#pragma unroll
  for (int j = 0; j < 4; ++j){
    int i = tid + j * 256; int r = i >> 3, v = i & 7;
    unsigned off = sw((unsigned)(r * 128 + v * 16));
    int ra = m0 + r; if (ra > D_ - 1) ra = D_ - 1;
    long ea = (long)ra * HW_ + k0 + v * 8;
    cpa16(st + off,         Ah + ea);
    cpa16(st + 16384 + off, Al + ea);
    int rb = n0 + r; if (rb > D_ - 1) rb = D_ - 1;
    long eb = (long)rb * HW_ + k0 + v * 8;
    cpa16(st + 32768 + off, Bh + eb);
    cpa16(st + 49152 + off, Bl + eb);
  }
}

__global__ void __launch_bounds__(256) gram_cp()
{
  extern __shared__ char raw[];
  unsigned rbase = su32(raw);
  char* dsm = raw + (((rbase + 1023u) & ~1023u) - rbase);
  const int tid = threadIdx.x, lane = tid & 31, wid = tid >> 5;
  const int wm = wid >> 2, wn = wid & 3;
  const int z = blockIdx.z, b = z & 15, b2 = (z < 16) ? b : ((b + 1) & 15);
  const int m0 = blockIdx.x * 128, n0 = blockIdx.y * 128;
  const bf* Ah = g_VsH + (long)b  * D_ * HW_;
  const bf* Al = g_VsL + (long)b  * D_ * HW_;
  const bf* Bh = g_VrH + (long)b2 * D_ * HW_;
  const bf* Bl = g_VrL + (long)b2 * D_ * HW_;

  float acc[4][4][4];
#pragma unroll
  for (int mi = 0; mi < 4; ++mi)
#pragma unroll
    for (int ni = 0; ni < 4; ++ni)
#pragma unroll
      for (int q = 0; q < 4; ++q) acc[mi][ni][q] = 0.f;

  unsigned sb = su32(dsm);
  const int NC = HW_ >> 6;
  fill_gram(sb,         Ah, Al, Bh, Bl, m0, n0, 0,  tid); cpc();
  fill_gram(sb + STAGE, Ah, Al, Bh, Bl, m0, n0, 64, tid); cpc();
  for (int c = 0; c < NC; ++c){
    if (c == NC - 1) cpw<0>(); else cpw<1>();
    __syncthreads();
    mma_chunk(sb + (c & 1) * STAGE, lane, wm, wn, acc);
    if (c + 2 < NC){
      __syncthreads();
      fill_gram(sb + (c & 1) * STAGE, Ah, Al, Bh, Bl, m0, n0, (c + 2) << 6, tid);
      cpc();
    }
  }

  float* Cg = g_G + (long)z * DSQ;
#pragma unroll
  for (int mi = 0; mi < 4; ++mi)
#pragma unroll
    for (int ni = 0; ni < 4; ++ni){
      float* c = acc[mi][ni];
      int r = m0 + wm * 64 + mi * 16 + (lane >> 2);
      int n = n0 + wn * 32 + ni * 8 + ((lane & 3) << 1);
      if (n < D_){
        if (r < D_)     *(float2*)(Cg + (long)r * D_ + n)       = make_float2(c[0], c[1]);
        if (r + 8 < D_) *(float2*)(Cg + (long)(r + 8) * D_ + n) = make_float2(c[2], c[3]);
      }
    }
}

// ---- final (cp.async): [v_asta; v_neg](896 x 4096) = [A'p;A'n] @ VrT^T per batch ----
__global__ void __launch_bounds__(256) final_cp(const float* __restrict__ Vs, float* __restrict__ out)
{
  extern __shared__ char raw[];
  unsigned rbase = su32(raw);
  char* dsm = raw + (((rbase + 1023u) & ~1023u) - rbase);
  const int tid = threadIdx.x, lane = tid & 31, wid = tid >> 5;
  const int wm = wid >> 2, wn = wid & 3;
  const int b = blockIdx.z;
  const int m0 = blockIdx.x * 128, n0 = blockIdx.y * 128;
  const bf* APh = g_AH + (long)b * DSQ;
  const bf* APl = g_AL + (long)b * DSQ;
  const bf* ANh = g_AH + (long)(16 + b) * DSQ;
  const bf* ANl = g_AL + (long)(16 + b) * DSQ;
  const bf* Bh  = g_VtH + (long)b * HW_ * D_;
  const bf* Bl  = g_VtL + (long)b * HW_ * D_;

  float acc[4][4][4];
#pragma unroll
  for (int mi = 0; mi < 4; ++mi)
#pragma unroll
    for (int ni = 0; ni < 4; ++ni)
#pragma unroll
      for (int q = 0; q < 4; ++q) acc[mi][ni][q] = 0.f;

  unsigned sb = su32(dsm);
  const int NC = D_ >> 6;  // 7
  // stacked-A fill: rows 0..895, pos<448, neg>=448; B rows always valid (4096)
  #define FILL_FIN(ST, K0) do { \
    _Pragma("unroll") \
    for (int j = 0; j < 4; ++j){ \
      int i = tid + j * 256; int r = i >> 3, v = i & 7; \
      unsigned off = sw((unsigned)(r * 128 + v * 16)); \
      int rg = m0 + r; \
      const bf* ph; const bf* pl; long ea; \
      if (rg < D_){ ph = APh; pl = APl; ea = (long)rg * D_ + (K0) + v * 8; } \
      else        { ph = ANh; pl = ANl; ea = (long)(rg - D_) * D_ + (K0) + v * 8; } \
      cpa16((ST) + off,         ph + ea); \
      cpa16((ST) + 16384 + off, pl + ea); \
      long eb = (long)(n0 + r) * D_ + (K0) + v * 8; \
      cpa16((ST) + 32768 + off, Bh + eb); \
      cpa16((ST) + 49152 + off, Bl + eb); \
    } } while(0)

  FILL_FIN(sb, 0); cpc();
  FILL_FIN(sb + STAGE, 64); cpc();
  for (int c = 0; c < NC; ++c){
    if (c == NC - 1) cpw<0>(); else cpw<1>();
    __syncthreads();
    mma_chunk(sb + (c & 1) * STAGE, lane, wm, wn, acc);
    if (c + 2 < NC){
      __syncthreads();
      FILL_FIN(sb + (c & 1) * STAGE, (c + 2) << 6);
      cpc();
    }
  }
  #undef FILL_FIN

#pragma unroll
  for (int mi = 0; mi < 4; ++mi)
#pragma unroll
    for (int ni = 0; ni < 4; ++ni){
      float* c = acc[mi][ni];
      int r = m0 + wm * 64 + mi * 16 + (lane >> 2);
      long n = n0 + wn * 32 + ni * 8 + ((lane & 3) << 1);
#pragma unroll
      for (int h = 0; h < 2; ++h){
        int rr = r + h * 8;
        float v0 = c[2*h], v1 = c[2*h + 1];
        if (rr < D_){
          long ix = ((long)b * D_ + rr) * HW_ + n;
          float2 vs = *(const float2*)(Vs + ix);
          *(float2*)(out + ix) = make_float2(vs.x + v0, vs.y + v1);
        } else {
          long ix = ((long)b * D_ + (rr - D_)) * HW_ + n;
          *(float2*)(g_neg + ix) = make_float2(v0, v1);
        }
      }
    }
}

// ================= R1 SIMT minis + softmax (validated, verbatim) =================
template<bool NT>
__device__ __forceinline__ void gemm_body(const float* __restrict__ A, const float* __restrict__ B,
                                          float* __restrict__ C, int K, int lda, int ldb, int ldc,
                                          float scale)
{
  __shared__ float As[16][68];
  __shared__ float Bs[16][68];
  const int tid = threadIdx.x;
  const int tx = tid & 15, ty = tid >> 4;
  const int m0 = blockIdx.x * 64, n0 = blockIdx.y * 64;
  unsigned long long acc[4][2];
#pragma unroll
  for (int i = 0; i < 4; i++) { acc[i][0] = 0ull; acc[i][1] = 0ull; }
  const int ra = tid >> 2, ka = tid & 3;
  const int kb = tid >> 4, nb = tid & 15;

  for (int k0 = 0; k0 < K; k0 += 16) {
    float4 av = *(const float4*)(A + (long)(m0 + ra) * lda + k0 + ka * 4);
    As[ka*4+0][ra] = av.x; As[ka*4+1][ra] = av.y; As[ka*4+2][ra] = av.z; As[ka*4+3][ra] = av.w;
    if (NT) {
      float4 bv = *(const float4*)(B + (long)(n0 + ra) * ldb + k0 + ka * 4);
      Bs[ka*4+0][ra] = bv.x; Bs[ka*4+1][ra] = bv.y; Bs[ka*4+2][ra] = bv.z; Bs[ka*4+3][ra] = bv.w;
    } else {
      *(float4*)&Bs[kb][nb*4] = *(const float4*)(B + (long)(k0 + kb) * ldb + n0 + nb * 4);
    }
    __syncthreads();
#pragma unroll
    for (int k = 0; k < 16; k++) {
      float4 a = *(const float4*)&As[k][ty*4];
      ulonglong2 bb = *(const ulonglong2*)&Bs[k][tx*4];
      unsigned long long a0 = pk2(a.x), a1 = pk2(a.y), a2 = pk2(a.z), a3 = pk2(a.w);
      fma2(acc[0][0], a0, bb.x); fma2(acc[0][1], a0, bb.y);
      fma2(acc[1][0], a1, bb.x); fma2(acc[1][1], a1, bb.y);
      fma2(acc[2][0], a2, bb.x); fma2(acc[2][1], a2, bb.y);
      fma2(acc[3][0], a3, bb.x); fma2(acc[3][1], a3, bb.y);
    }
    __syncthreads();
  }
#pragma unroll
  for (int i = 0; i < 4; i++) {
    float2 lo = up2(acc[i][0]), hi = up2(acc[i][1]);
    float4 o = make_float4(lo.x*scale, lo.y*scale, hi.x*scale, hi.y*scale);
    *(float4*)(C + (long)(m0 + ty*4 + i) * ldc + n0 + tx*4) = o;
  }
}

__global__ void __launch_bounds__(256) gkt_kernel(const float* __restrict__ Wk)
{
  int z = blockIdx.z;
  gemm_body<true>(g_G + (long)z * DSQ, Wk, g_T + (long)z * DSQ, D_, D_, D_, D_, 1.0f);
}

__global__ void __launch_bounds__(256) wqt_kernel(const float* __restrict__ Wq)
{
  int z = blockIdx.z;
  const float SCALE = 0.047245559f;
  gemm_body<false>(Wq, g_T + (long)z * DSQ, g_S + (long)z * DSQ, D_, D_, D_, D_, SCALE);
}

__global__ void __launch_bounds__(256) softmax_kernel()
{
  int warp = (blockIdx.x * blockDim.x + threadIdx.x) >> 5;
  int lane = threadIdx.x & 31;
  if (warp >= 32 * D_) return;
  float* row = g_S + (long)warp * D_;
  float v[14];
  float mx = -1e30f;
#pragma unroll
  for (int i = 0; i < 14; i++) { v[i] = row[lane + i * 32]; mx = fmaxf(mx, v[i]); }
#pragma unroll
  for (int o = 16; o; o >>= 1) mx = fmaxf(mx, __shfl_xor_sync(0xffffffffu, mx, o));
  float s = 0.f;
#pragma unroll
  for (int i = 0; i < 14; i++) { v[i] = __expf(v[i] - mx); s += v[i]; }
#pragma unroll
  for (int o = 16; o; o >>= 1) s += __shfl_xor_sync(0xffffffffu, s, o);
  float inv = 1.0f / s;
#pragma unroll
  for (int i = 0; i < 14; i++) row[lane + i * 32] = v[i] * inv;
}

__global__ void __launch_bounds__(256) av_kernel(const float* __restrict__ Wv)
{
  int z = blockIdx.z;
  gemm_body<false>(g_S + (long)z * DSQ, Wv, g_A + (long)z * DSQ, D_, D_, D_, D_, 1.0f);
}

// ---- loss: deterministic two-stage reduction over out/Vs/g_neg ----
__global__ void __launch_bounds__(256) loss_partial(const float* __restrict__ Vs,
                                                    const float* __restrict__ out)
{
  __shared__ float red[256];
  const int tid = threadIdx.x;
  float l = 0.f;
  for (long i = blockIdx.x * 256L + tid; i < BIG; i += NLOSS * 256L){
    float pos = out[i] - Vs[i];
    l += fmaxf(g_neg[i] - pos + 12.0f, 0.0f);
  }
  red[tid] = l; __syncthreads();
  for (int s = 128; s; s >>= 1){ if (tid < s) red[tid] += red[tid + s]; __syncthreads(); }
  if (tid == 0) g_part[blockIdx.x] = red[0];
}

__global__ void __launch_bounds__(256) loss_final(float* __restrict__ out, int out_size)
{
  __shared__ float red[256];
  const int tid = threadIdx.x;
  float s = 0.f;
  for (int i = tid; i < NLOSS; i += 256) s += g_part[i];
  red[tid] = s; __syncthreads();
  for (int st = 128; st; st >>= 1){ if (tid < st) red[tid] += red[tid + st]; __syncthreads(); }
  if (tid == 0 && (long)out_size > NOUT) out[NOUT] = red[0] * (1.0f / (float)BIG);
}

extern "C" void kernel_launch(void* const* d_in, const int* in_sizes, int n_in,
                              void* d_out, int out_size)
{
  (void)in_sizes; (void)n_in;
  const float* V_r = (const float*)d_in[0];
  const float* V_s = (const float*)d_in[1];
  const float* W_q = (const float*)d_in[2];
  const float* W_k = (const float*)d_in[3];
  const float* W_v = (const float*)d_in[4];
  float* out = (float*)d_out;

  cudaFuncSetAttribute(gram_cp,  cudaFuncAttributeMaxDynamicSharedMemorySize, MSMEM);
  cudaFuncSetAttribute(final_cp, cudaFuncAttributeMaxDynamicSharedMemorySize, MSMEM);

  dim3 blk(256);
  split_Vs<<<512, blk>>>(V_s);
  split_Vr<<<512, blk>>>(V_r);
  trans_split<<<dim3(128, 14, 16), dim3(32, 8)>>>(V_r);

  gram_cp<<<dim3(4, 4, 32), blk, MSMEM>>>();
  gkt_kernel<<<dim3(7, 7, 32), blk>>>(W_k);
  wqt_kernel<<<dim3(7, 7, 32), blk>>>(W_q);
  softmax_kernel<<<1792, blk>>>();
  av_kernel<<<dim3(7, 7, 32), blk>>>(W_v);
  split_A<<<512, blk>>>();

  final_cp<<<dim3(7, 32, 16), blk, MSMEM>>>(V_s, out);
  loss_partial<<<NLOSS, blk>>>(V_s, out);
  loss_final<<<1, blk>>>(out, out_size);
}